// round 15
// baseline (speedup 1.0000x reference)
#include <cuda_runtime.h>
#include <cuda_fp16.h>
#include <cstdint>
#include <math.h>

// ---------------------------------------------------------------------------
// TransformerBlock: B=2, C=384, N=2048 tokens/batch, H=8 heads, d=48
// fp32 I/O + residual stream, fp16 mma.m16n8k16 + ldmatrix + cp.async.
// R15: R14 + BK=64 for the BM=64 GEMMs (Wo, W2) — halves barrier count.
// ---------------------------------------------------------------------------

#define BATCH   2
#define DIM     384
#define NTOK    2048
#define MTOT    (BATCH * NTOK)  // 4096
#define NHEADS  8
#define BH      (BATCH * NHEADS)  // 16
#define HDIM    48
#define QKVC    (3 * DIM)       // 1152
#define MLPH    1536
#define ATT_C   (0.14433756729740643f * 1.4426950408889634f)   // scale*log2(e)
#define SPLIT   2
#define TILES_PER_SPLIT (NTOK / 64 / SPLIT)   // 16
#define ONES_H2 0x3C003C00u     // half2(1.0, 1.0)

// ----------------------------- scratch ------------------------------------
__device__ float  g_h   [MTOT * DIM];
__device__ __half g_hnb [MTOT * DIM];
__device__ __half g_qkvb[MTOT * QKVC];
__device__ __half g_attb[MTOT * DIM];
__device__ __half g_mlpb[MTOT * MLPH];
__device__ __half g_wqkv[QKVC * DIM];   // transposed [N][K]
__device__ __half g_wo  [DIM * DIM];
__device__ __half g_w1  [MLPH * DIM];
__device__ __half g_w2  [DIM * MLPH];
__device__ __half g_po[SPLIT * BH * NTOK * HDIM];   // fp16 partial O
__device__ float  g_pm[SPLIT * BH * NTOK];
__device__ float  g_pl[SPLIT * BH * NTOK];

// --------------------------- asm helpers -----------------------------------
__device__ __forceinline__ void mma16(float* c, const uint32_t* a,
                                      uint32_t b0, uint32_t b1) {
    asm volatile(
        "mma.sync.aligned.m16n8k16.row.col.f32.f16.f16.f32 "
        "{%0,%1,%2,%3}, {%4,%5,%6,%7}, {%8,%9}, {%0,%1,%2,%3};\n"
        : "+f"(c[0]), "+f"(c[1]), "+f"(c[2]), "+f"(c[3])
        : "r"(a[0]), "r"(a[1]), "r"(a[2]), "r"(a[3]), "r"(b0), "r"(b1));
}
__device__ __forceinline__ uint32_t ex2h2(float a, float b) {
    __half2 h = __floats2half2_rn(a, b);
    uint32_t u = *(uint32_t*)&h, r;
    asm("ex2.approx.f16x2 %0, %1;" : "=r"(r) : "r"(u));
    return r;
}
__device__ __forceinline__ uint32_t smaddr(const void* p) {
    return (uint32_t)__cvta_generic_to_shared(p);
}
__device__ __forceinline__ void ldsm4(uint32_t* r, uint32_t a) {
    asm volatile("ldmatrix.sync.aligned.m8n8.x4.shared.b16 {%0,%1,%2,%3}, [%4];"
                 : "=r"(r[0]), "=r"(r[1]), "=r"(r[2]), "=r"(r[3]) : "r"(a));
}
__device__ __forceinline__ void ldsm4t(uint32_t* r, uint32_t a) {
    asm volatile("ldmatrix.sync.aligned.m8n8.x4.trans.shared.b16 {%0,%1,%2,%3}, [%4];"
                 : "=r"(r[0]), "=r"(r[1]), "=r"(r[2]), "=r"(r[3]) : "r"(a));
}
__device__ __forceinline__ void cpasync16(uint32_t dst, const void* src) {
    asm volatile("cp.async.ca.shared.global [%0], [%1], 16;\n" :: "r"(dst), "l"(src));
}
__device__ __forceinline__ void cpcommit() { asm volatile("cp.async.commit_group;\n"); }
__device__ __forceinline__ void cpwait1()  { asm volatile("cp.async.wait_group 1;\n"); }
__device__ __forceinline__ void cpwait0()  { asm volatile("cp.async.wait_group 0;\n"); }

// ------------------ fused weight prep: fp32 [R][C] -> fp16 [C][R] ----------
__global__ void k_wprep_all(const float* __restrict__ Wqkv, const float* __restrict__ Wo,
                            const float* __restrict__ W1, const float* __restrict__ W2,
                            __half* __restrict__ wqkv, __half* __restrict__ wo,
                            __half* __restrict__ w1, __half* __restrict__ w2)
{
    __shared__ float t[32][33];
    int bid = blockIdx.x;
    const float* in; __half* out; int R, C, rb, cb;
    if (bid < 432)       { int id = bid;        in = Wqkv; out = wqkv; R = 384;  C = 1152; cb = id % 36; rb = id / 36; }
    else if (bid < 576)  { int id = bid - 432;  in = Wo;   out = wo;   R = 384;  C = 384;  cb = id % 12; rb = id / 12; }
    else if (bid < 1152) { int id = bid - 576;  in = W1;   out = w1;   R = 384;  C = 1536; cb = id % 48; rb = id / 48; }
    else                 { int id = bid - 1152; in = W2;   out = w2;   R = 1536; C = 384;  cb = id % 12; rb = id / 12; }

    const int c = cb * 32 + threadIdx.x;
    #pragma unroll
    for (int j = 0; j < 4; j++) {
        int r = rb * 32 + threadIdx.y + j * 8;
        t[threadIdx.y + j * 8][threadIdx.x] = in[(size_t)r * C + c];
    }
    __syncthreads();
    const int r2 = rb * 32 + threadIdx.x;
    #pragma unroll
    for (int j = 0; j < 4; j++) {
        int c2 = cb * 32 + threadIdx.y + j * 8;
        out[(size_t)c2 * R + r2] = __float2half(t[threadIdx.x][threadIdx.y + j * 8]);
    }
}

// ------------------ kernel 1: transpose + LN1 (no h write) -----------------
#define TT 16
__global__ void k_transpose_ln(const float* __restrict__ x,
                               const float* __restrict__ g,
                               const float* __restrict__ b,
                               __half* __restrict__ hn)
{
    __shared__ float tile[TT][DIM + 1];
    const int tilesPerBatch = NTOK / TT;
    const int bb = blockIdx.x / tilesPerBatch;
    const int n0 = (blockIdx.x % tilesPerBatch) * TT;
    const float* xb = x + (size_t)bb * DIM * NTOK;

    for (int idx = threadIdx.x; idx < DIM * TT; idx += blockDim.x) {
        int c = idx / TT, t = idx % TT;
        tile[t][c] = xb[(size_t)c * NTOK + n0 + t];
    }
    __syncthreads();

    const int wid = threadIdx.x >> 5, lane = threadIdx.x & 31;
    for (int t = wid; t < TT; t += (int)(blockDim.x >> 5)) {
        float s = 0.f;
        #pragma unroll
        for (int c = lane; c < DIM; c += 32) s += tile[t][c];
        #pragma unroll
        for (int o = 16; o; o >>= 1) s += __shfl_xor_sync(0xffffffffu, s, o);
        float mu = s * (1.f / DIM);
        float vs = 0.f;
        #pragma unroll
        for (int c = lane; c < DIM; c += 32) { float d = tile[t][c] - mu; vs += d * d; }
        #pragma unroll
        for (int o = 16; o; o >>= 1) vs += __shfl_xor_sync(0xffffffffu, vs, o);
        float rstd = rsqrtf(vs * (1.f / DIM) + 1e-6f);
        size_t row = ((size_t)bb * NTOK + n0 + t) * DIM;
        for (int c = lane; c < DIM; c += 32) {
            hn[row + c] = __float2half((tile[t][c] - mu) * rstd * g[c] + b[c]);
        }
    }
}

// ----------------- kernel 2: fp16 GEMM (ldmatrix + cp.async) ---------------
// BKT: 32 (BM=128) or 64 (BM=64). RESTR/OUTTR: transposed residual/output.
template<int BM, int BKT, bool BIAS, bool GELU_, bool RES, bool RESTR, bool OUTHF, bool OUTTR>
__global__ void __launch_bounds__(256)
k_gemm(const __half* __restrict__ A, const __half* __restrict__ Bt,
       const float* __restrict__ bias, const float* __restrict__ res,
       void* __restrict__ Cout, int M, int N, int K)
{
    constexpr int BN = 64;
    constexpr int SA = BKT + 8;             // 40 or 72: conflict-free strides
    constexpr int MW = BM / 32;
    constexpr int WN = BN / (8 / MW);
    constexpr int NS = WN / 8;
    constexpr int KK = BKT / 16;            // 2 or 4 k-chunks
    __shared__ __half As[2][BM * SA];
    __shared__ __half Bs[2][BN * SA];

    const int tid = threadIdx.x;
    const int m0 = blockIdx.y * BM, n0 = blockIdx.x * BN;
    const int wid = tid >> 5, lane = tid & 31;
    const int g = lane >> 2, tg = lane & 3;
    const int wm0 = (wid % MW) * 32;
    const int wn0 = (wid / MW) * WN;
    const int lr = lane & 15, lk = (lane >> 4) * 8;

    float acc[2][NS][4];
    #pragma unroll
    for (int i = 0; i < 2; i++)
        #pragma unroll
        for (int j = 0; j < NS; j++)
            #pragma unroll
            for (int q = 0; q < 4; q++) acc[i][j][q] = 0.f;

    // load mapping: BKT=32 -> 8 halves/thread/matrix; BKT=64 -> 16 halves
    const int a_r = tid >> 2;
    const int a_c = (tid & 3) * (BKT / 4);
    const __half* Ap = A  + (size_t)(m0 + a_r) * K + a_c;
    const __half* Bp = Bt + (size_t)(n0 + a_r) * K + a_c;

    auto issue = [&](int buf, int koff) {
        uint32_t dA = smaddr(&As[buf][a_r * SA + a_c]);
        uint32_t dB = smaddr(&Bs[buf][a_r * SA + a_c]);
        cpasync16(dA, Ap + koff);
        if (BKT == 64) cpasync16(dA + 16, Ap + koff + 8);
        if (BM == 128) {
            uint32_t dA2 = smaddr(&As[buf][(a_r + 64) * SA + a_c]);
            cpasync16(dA2, Ap + (size_t)64 * K + koff);
            if (BKT == 64) cpasync16(dA2 + 16, Ap + (size_t)64 * K + koff + 8);
        }
        cpasync16(dB, Bp + koff);
        if (BKT == 64) cpasync16(dB + 16, Bp + koff + 8);
        cpcommit();
    };

    const int ntiles = K / BKT;
    issue(0, 0);

    for (int t = 0; t < ntiles; t++) {
        const int cur = t & 1;
        if (t + 1 < ntiles) {
            issue(cur ^ 1, (t + 1) * BKT);
            cpwait1();
        } else {
            cpwait0();
        }
        __syncthreads();

        #pragma unroll
        for (int kk = 0; kk < KK; kk++) {
            uint32_t af[2][4];
            #pragma unroll
            for (int ms = 0; ms < 2; ms++)
                ldsm4(af[ms], smaddr(&As[cur][(wm0 + ms * 16 + lr) * SA + kk * 16 + lk]));
            #pragma unroll
            for (int p = 0; p < NS / 2; p++) {
                uint32_t bf[4];
                ldsm4(bf, smaddr(&Bs[cur][(wn0 + p * 16 + lr) * SA + kk * 16 + lk]));
                #pragma unroll
                for (int ms = 0; ms < 2; ms++) {
                    mma16(acc[ms][2 * p],     af[ms], bf[0], bf[2]);
                    mma16(acc[ms][2 * p + 1], af[ms], bf[1], bf[3]);
                }
            }
        }
        __syncthreads();
    }

    #pragma unroll
    for (int ms = 0; ms < 2; ms++) {
        #pragma unroll
        for (int rr = 0; rr < 2; rr++) {
            size_t m = (size_t)m0 + wm0 + ms * 16 + g + rr * 8;
            #pragma unroll
            for (int ns = 0; ns < NS; ns++) {
                int n = n0 + wn0 + ns * 8 + tg * 2;
                float v0 = acc[ms][ns][rr * 2 + 0];
                float v1 = acc[ms][ns][rr * 2 + 1];
                if (BIAS) { v0 += bias[n]; v1 += bias[n + 1]; }
                if (GELU_) {
                    v0 = 0.5f * v0 * (1.f + erff(v0 * 0.70710678118654752f));
                    v1 = 0.5f * v1 * (1.f + erff(v1 * 0.70710678118654752f));
                }
                if (RES) {
                    if (RESTR) {
                        int bbb = (int)(m >> 11), tok = (int)(m & (NTOK - 1));
                        v0 += res[((size_t)bbb * DIM + n) * NTOK + tok];
                        v1 += res[((size_t)bbb * DIM + n + 1) * NTOK + tok];
                    } else {
                        v0 += res[m * N + n];
                        v1 += res[m * N + n + 1];
                    }
                }
                if (OUTTR) {
                    int bbb = (int)(m >> 11), tok = (int)(m & (NTOK - 1));
                    float* op = (float*)Cout + ((size_t)bbb * DIM + n) * NTOK + tok;
                    op[0] = v0;
                    op[NTOK] = v1;
                } else if (OUTHF) {
                    *(__half2*)((__half*)Cout + m * N + n) = __floats2half2_rn(v0, v1);
                } else {
                    *(float2*)((float*)Cout + m * N + n) = make_float2(v0, v1);
                }
            }
        }
    }
}

// ---------------- kernel 3: split-KV fp16 flash attention ------------------
__global__ void __launch_bounds__(128)
k_attn(const __half* __restrict__ qkv,
       __half* __restrict__ po, float* __restrict__ pm, float* __restrict__ pl)
{
    constexpr int SQ = 56;
    __shared__ __half Ks[2][64 * SQ];
    __shared__ __half Vs[2][64 * SQ];

    const int bh = blockIdx.y;
    const int sp = blockIdx.z;
    const int bb = bh >> 3, hh = bh & 7;
    const __half* base = qkv + (size_t)bb * NTOK * QKVC + hh * HDIM;
    const __half* kvbase = base + (size_t)sp * TILES_PER_SPLIT * 64 * QKVC;
    const int q0 = blockIdx.x * 64;
    const int tid = threadIdx.x;
    const int w = tid >> 5, lane = tid & 31;
    const int g = lane >> 2, tg = lane & 3;
    const int wrow0 = w * 16;
    const int lr = lane & 15, lk = (lane >> 4) * 8;

    #pragma unroll
    for (int j = 0; j < 3; j++) {
        int idx = tid + j * 128;
        int r = idx / 6, c8 = (idx % 6) * 8;
        *(uint4*)&Ks[0][r * SQ + c8] = *(const uint4*)(base + (size_t)(q0 + r) * QKVC + c8);
    }
    __syncthreads();
    uint32_t aq[3][4];
    #pragma unroll
    for (int kc = 0; kc < 3; kc++)
        ldsm4(aq[kc], smaddr(&Ks[0][(wrow0 + lr) * SQ + kc * 16 + lk]));
    __syncthreads();

    const int r0i = (tid) / 6, c0i = ((tid) % 6) * 8;
    const int r1i = (tid + 128) / 6, c1i = ((tid + 128) % 6) * 8;
    const int r2i = (tid + 256) / 6, c2i = ((tid + 256) % 6) * 8;
    const size_t o0 = (size_t)r0i * QKVC + c0i;
    const size_t o1 = (size_t)r1i * QKVC + c1i;
    const size_t o2 = (size_t)r2i * QKVC + c2i;

    cpasync16(smaddr(&Ks[0][r0i * SQ + c0i]), kvbase + o0 + DIM);
    cpasync16(smaddr(&Ks[0][r1i * SQ + c1i]), kvbase + o1 + DIM);
    cpasync16(smaddr(&Ks[0][r2i * SQ + c2i]), kvbase + o2 + DIM);
    cpasync16(smaddr(&Vs[0][r0i * SQ + c0i]), kvbase + o0 + 2 * DIM);
    cpasync16(smaddr(&Vs[0][r1i * SQ + c1i]), kvbase + o1 + 2 * DIM);
    cpasync16(smaddr(&Vs[0][r2i * SQ + c2i]), kvbase + o2 + 2 * DIM);
    cpcommit();

    float oacc[6][4], lacc[4];
    #pragma unroll
    for (int i = 0; i < 6; i++)
        #pragma unroll
        for (int j = 0; j < 4; j++) oacc[i][j] = 0.f;
    #pragma unroll
    for (int j = 0; j < 4; j++) lacc[j] = 0.f;
    float mA = -1e30f, mB = -1e30f;

    for (int kt = 0; kt < TILES_PER_SPLIT; kt++) {
        const int cur = kt & 1;
        if (kt + 1 < TILES_PER_SPLIT) {
            const __half* nb = kvbase + (size_t)(kt + 1) * 64 * QKVC;
            cpasync16(smaddr(&Ks[cur ^ 1][r0i * SQ + c0i]), nb + o0 + DIM);
            cpasync16(smaddr(&Ks[cur ^ 1][r1i * SQ + c1i]), nb + o1 + DIM);
            cpasync16(smaddr(&Ks[cur ^ 1][r2i * SQ + c2i]), nb + o2 + DIM);
            cpasync16(smaddr(&Vs[cur ^ 1][r0i * SQ + c0i]), nb + o0 + 2 * DIM);
            cpasync16(smaddr(&Vs[cur ^ 1][r1i * SQ + c1i]), nb + o1 + 2 * DIM);
            cpasync16(smaddr(&Vs[cur ^ 1][r2i * SQ + c2i]), nb + o2 + 2 * DIM);
            cpcommit();
            cpwait1();
        } else {
            cpwait0();
        }
        __syncthreads();

        float sacc[8][4];
        #pragma unroll
        for (int ns = 0; ns < 8; ns++)
            #pragma unroll
            for (int q = 0; q < 4; q++) sacc[ns][q] = 0.f;
        #pragma unroll
        for (int kc = 0; kc < 3; kc++) {
            #pragma unroll
            for (int p = 0; p < 4; p++) {
                uint32_t bk[4];
                ldsm4(bk, smaddr(&Ks[cur][(p * 16 + lr) * SQ + kc * 16 + lk]));
                mma16(sacc[2 * p],     aq[kc], bk[0], bk[2]);
                mma16(sacc[2 * p + 1], aq[kc], bk[1], bk[3]);
            }
        }

        float rmaxA = -1e30f, rmaxB = -1e30f;
        #pragma unroll
        for (int ns = 0; ns < 8; ns++) {
            rmaxA = fmaxf(rmaxA, fmaxf(sacc[ns][0], sacc[ns][1]));
            rmaxB = fmaxf(rmaxB, fmaxf(sacc[ns][2], sacc[ns][3]));
        }
        rmaxA = fmaxf(rmaxA, __shfl_xor_sync(0xffffffffu, rmaxA, 1));
        rmaxA = fmaxf(rmaxA, __shfl_xor_sync(0xffffffffu, rmaxA, 2));
        rmaxB = fmaxf(rmaxB, __shfl_xor_sync(0xffffffffu, rmaxB, 1));
        rmaxB = fmaxf(rmaxB, __shfl_xor_sync(0xffffffffu, rmaxB, 2));

        float mAn = fmaxf(mA, rmaxA), mBn = fmaxf(mB, rmaxB);
        float fA = exp2f((mA - mAn) * ATT_C), fB = exp2f((mB - mBn) * ATT_C);
        mA = mAn; mB = mBn;
        const float nmcA = -mA * ATT_C, nmcB = -mB * ATT_C;

        uint32_t pA[8], pB[8];
        #pragma unroll
        for (int ns = 0; ns < 8; ns++) {
            pA[ns] = ex2h2(fmaf(sacc[ns][0], ATT_C, nmcA),
                           fmaf(sacc[ns][1], ATT_C, nmcA));
            pB[ns] = ex2h2(fmaf(sacc[ns][2], ATT_C, nmcB),
                           fmaf(sacc[ns][3], ATT_C, nmcB));
        }

        #pragma unroll
        for (int ns = 0; ns < 6; ns++) {
            oacc[ns][0] *= fA; oacc[ns][1] *= fA;
            oacc[ns][2] *= fB; oacc[ns][3] *= fB;
        }
        lacc[0] *= fA; lacc[1] *= fA; lacc[2] *= fB; lacc[3] *= fB;

        #pragma unroll
        for (int kc = 0; kc < 4; kc++) {
            uint32_t ap[4] = { pA[2 * kc], pB[2 * kc], pA[2 * kc + 1], pB[2 * kc + 1] };
            #pragma unroll
            for (int p = 0; p < 3; p++) {
                uint32_t bv[4];
                ldsm4t(bv, smaddr(&Vs[cur][(kc * 16 + lr) * SQ + p * 16 + lk]));
                mma16(oacc[2 * p],     ap, bv[0], bv[1]);
                mma16(oacc[2 * p + 1], ap, bv[2], bv[3]);
            }
            mma16(lacc, ap, ONES_H2, ONES_H2);
        }
        __syncthreads();
    }

    const size_t prowA = ((size_t)(sp * BH + bh) * NTOK) + q0 + wrow0 + g;
    #pragma unroll
    for (int ns = 0; ns < 6; ns++) {
        int col = ns * 8 + tg * 2;
        *(__half2*)&po[prowA * HDIM + col] = __floats2half2_rn(oacc[ns][0], oacc[ns][1]);
        *(__half2*)&po[(prowA + 8) * HDIM + col] = __floats2half2_rn(oacc[ns][2], oacc[ns][3]);
    }
    if (tg == 0) {
        pm[prowA] = mA; pl[prowA] = lacc[0];
        pm[prowA + 8] = mB; pl[prowA + 8] = lacc[2];
    }
}

// ---------------- kernel 3b: split-KV merge (SPLIT partials) ---------------
__global__ void k_attn_merge(const __half* __restrict__ po, const float* __restrict__ pm,
                             const float* __restrict__ pl, __half* __restrict__ attn)
{
    const int e = blockIdx.x * 256 + threadIdx.x;
    if (e >= BH * NTOK * HDIM) return;
    const int d = e % HDIM;
    const int row = e / HDIM;
    float m = -1e30f;
    #pragma unroll
    for (int s = 0; s < SPLIT; s++) m = fmaxf(m, pm[s * BH * NTOK + row]);
    float num = 0.f, den = 0.f;
    #pragma unroll
    for (int s = 0; s < SPLIT; s++) {
        const float ws = exp2f((pm[s * BH * NTOK + row] - m) * ATT_C);
        num += __half2float(po[((size_t)s * BH * NTOK + row) * HDIM + d]) * ws;
        den += pl[s * BH * NTOK + row] * ws;
    }
    const float o = num / den;
    const int bh = row >> 11, q = row & (NTOK - 1);
    const int bb = bh >> 3, hh = bh & 7;
    attn[((size_t)(bb * NTOK + q)) * DIM + hh * HDIM + d] = __float2half(o);
}

// --------------------------- kernel 4: LN ---------------------------------
__global__ void k_ln(const float* __restrict__ in, const float* __restrict__ g,
                     const float* __restrict__ b, __half* __restrict__ out)
{
    const int row = blockIdx.x;
    const float* p = in + (size_t)row * DIM;
    const int t = threadIdx.x;
    float v0 = p[t], v1 = p[t + 128], v2 = p[t + 256];
    float s = v0 + v1 + v2;

    __shared__ float red[4];
    #pragma unroll
    for (int o = 16; o; o >>= 1) s += __shfl_xor_sync(0xffffffffu, s, o);
    if ((t & 31) == 0) red[t >> 5] = s;
    __syncthreads();
    float mu = (red[0] + red[1] + red[2] + red[3]) * (1.f / DIM);

    float d0 = v0 - mu, d1 = v1 - mu, d2 = v2 - mu;
    float q = d0 * d0 + d1 * d1 + d2 * d2;
    __syncthreads();
    #pragma unroll
    for (int o = 16; o; o >>= 1) q += __shfl_xor_sync(0xffffffffu, q, o);
    if ((t & 31) == 0) red[t >> 5] = q;
    __syncthreads();
    float rstd = rsqrtf((red[0] + red[1] + red[2] + red[3]) * (1.f / DIM) + 1e-6f);

    __half* po = out + (size_t)row * DIM;
    po[t]       = __float2half(d0 * rstd * g[t]       + b[t]);
    po[t + 128] = __float2half(d1 * rstd * g[t + 128] + b[t + 128]);
    po[t + 256] = __float2half(d2 * rstd * g[t + 256] + b[t + 256]);
}

// ------------------------------- launch ------------------------------------
extern "C" void kernel_launch(void* const* d_in, const int* in_sizes, int n_in,
                              void* d_out, int out_size)
{
    const float* x    = (const float*)d_in[0];
    const float* g1   = (const float*)d_in[1];
    const float* b1   = (const float*)d_in[2];
    const float* Wqkv = (const float*)d_in[3];
    const float* Wo   = (const float*)d_in[4];
    const float* bo   = (const float*)d_in[5];
    const float* g2   = (const float*)d_in[6];
    const float* b2   = (const float*)d_in[7];
    const float* W1   = (const float*)d_in[8];
    const float* b1m  = (const float*)d_in[9];
    const float* W2   = (const float*)d_in[10];
    const float* b2m  = (const float*)d_in[11];
    float* out = (float*)d_out;

    float *h, *pm, *pl;
    __half *hnb, *qkvb, *attb, *mlpb, *wqkv, *wo, *w1, *w2, *po;
    cudaGetSymbolAddress((void**)&h,    g_h);
    cudaGetSymbolAddress((void**)&hnb,  g_hnb);
    cudaGetSymbolAddress((void**)&qkvb, g_qkvb);
    cudaGetSymbolAddress((void**)&attb, g_attb);
    cudaGetSymbolAddress((void**)&mlpb, g_mlpb);
    cudaGetSymbolAddress((void**)&wqkv, g_wqkv);
    cudaGetSymbolAddress((void**)&wo,   g_wo);
    cudaGetSymbolAddress((void**)&w1,   g_w1);
    cudaGetSymbolAddress((void**)&w2,   g_w2);
    cudaGetSymbolAddress((void**)&po,   g_po);
    cudaGetSymbolAddress((void**)&pm,   g_pm);
    cudaGetSymbolAddress((void**)&pl,   g_pl);

    k_wprep_all<<<1728, dim3(32, 8)>>>(Wqkv, Wo, W1, W2, wqkv, wo, w1, w2);

    // 1. transpose + LN1 (hn only)
    k_transpose_ln<<<MTOT / TT, 256>>>(x, g1, b1, hnb);
    // 2. qkv = hn @ Wqkv  (BM=128, BK=32)
    k_gemm<128, 32, false, false, false, false, true, false>
        <<<dim3(QKVC / 64, MTOT / 128), 256>>>(
        hnb, wqkv, nullptr, nullptr, qkvb, MTOT, QKVC, DIM);
    // 3. attention (split-KV x2) + merge
    k_attn<<<dim3(NTOK / 64, BH, SPLIT), 128>>>(qkvb, po, pm, pl);
    k_attn_merge<<<(BH * NTOK * HDIM + 255) / 256, 256>>>(po, pm, pl, attb);
    // 4. h = x(transposed) + att @ Wo + bo  (BM=64, BK=64)
    k_gemm<64, 64, true, false, true, true, false, false>
        <<<dim3(DIM / 64, MTOT / 64), 256>>>(
        attb, wo, bo, x, h, MTOT, DIM, DIM);
    // 5. LN2
    k_ln<<<MTOT, 128>>>(h, g2, b2, hnb);
    // 6. mlp = gelu(hn @ W1 + b1m)  (BM=128, BK=32)
    k_gemm<128, 32, true, true, false, false, true, false>
        <<<dim3(MLPH / 64, MTOT / 128), 256>>>(
        hnb, w1, b1m, nullptr, mlpb, MTOT, MLPH, DIM);
    // 7. out = transpose(h + mlp @ W2 + b2m)  (BM=64, BK=64)
    k_gemm<64, 64, true, false, true, false, false, true>
        <<<dim3(DIM / 64, MTOT / 64), 256>>>(
        mlpb, w2, b2m, h, out, MTOT, DIM, MLPH);
}

// round 16
// speedup vs baseline: 1.0152x; 1.0152x over previous
#include <cuda_runtime.h>
#include <cuda_fp16.h>
#include <cstdint>
#include <math.h>

// ---------------------------------------------------------------------------
// TransformerBlock: B=2, C=384, N=2048 tokens/batch, H=8 heads, d=48
// fp32 I/O + residual stream, fp16 mma.m16n8k16 + ldmatrix + cp.async.
// R16: R14 anchor + fused prep kernel (wprep+transpose_ln) + half2 merge.
// ---------------------------------------------------------------------------

#define BATCH   2
#define DIM     384
#define NTOK    2048
#define MTOT    (BATCH * NTOK)  // 4096
#define NHEADS  8
#define BH      (BATCH * NHEADS)  // 16
#define HDIM    48
#define QKVC    (3 * DIM)       // 1152
#define MLPH    1536
#define ATT_C   (0.14433756729740643f * 1.4426950408889634f)   // scale*log2(e)
#define SPLIT   2
#define TILES_PER_SPLIT (NTOK / 64 / SPLIT)   // 16
#define ONES_H2 0x3C003C00u     // half2(1.0, 1.0)
#define WPREP_BLOCKS 1728
#define TT 16

// ----------------------------- scratch ------------------------------------
__device__ float  g_h   [MTOT * DIM];
__device__ __half g_hnb [MTOT * DIM];
__device__ __half g_qkvb[MTOT * QKVC];
__device__ __half g_attb[MTOT * DIM];
__device__ __half g_mlpb[MTOT * MLPH];
__device__ __half g_wqkv[QKVC * DIM];   // transposed [N][K]
__device__ __half g_wo  [DIM * DIM];
__device__ __half g_w1  [MLPH * DIM];
__device__ __half g_w2  [DIM * MLPH];
__device__ __half g_po[SPLIT * BH * NTOK * HDIM];   // fp16 partial O
__device__ float  g_pm[SPLIT * BH * NTOK];
__device__ float  g_pl[SPLIT * BH * NTOK];

// --------------------------- asm helpers -----------------------------------
__device__ __forceinline__ void mma16(float* c, const uint32_t* a,
                                      uint32_t b0, uint32_t b1) {
    asm volatile(
        "mma.sync.aligned.m16n8k16.row.col.f32.f16.f16.f32 "
        "{%0,%1,%2,%3}, {%4,%5,%6,%7}, {%8,%9}, {%0,%1,%2,%3};\n"
        : "+f"(c[0]), "+f"(c[1]), "+f"(c[2]), "+f"(c[3])
        : "r"(a[0]), "r"(a[1]), "r"(a[2]), "r"(a[3]), "r"(b0), "r"(b1));
}
__device__ __forceinline__ uint32_t ex2h2(float a, float b) {
    __half2 h = __floats2half2_rn(a, b);
    uint32_t u = *(uint32_t*)&h, r;
    asm("ex2.approx.f16x2 %0, %1;" : "=r"(r) : "r"(u));
    return r;
}
__device__ __forceinline__ uint32_t smaddr(const void* p) {
    return (uint32_t)__cvta_generic_to_shared(p);
}
__device__ __forceinline__ void ldsm4(uint32_t* r, uint32_t a) {
    asm volatile("ldmatrix.sync.aligned.m8n8.x4.shared.b16 {%0,%1,%2,%3}, [%4];"
                 : "=r"(r[0]), "=r"(r[1]), "=r"(r[2]), "=r"(r[3]) : "r"(a));
}
__device__ __forceinline__ void ldsm4t(uint32_t* r, uint32_t a) {
    asm volatile("ldmatrix.sync.aligned.m8n8.x4.trans.shared.b16 {%0,%1,%2,%3}, [%4];"
                 : "=r"(r[0]), "=r"(r[1]), "=r"(r[2]), "=r"(r[3]) : "r"(a));
}
__device__ __forceinline__ void cpasync16(uint32_t dst, const void* src) {
    asm volatile("cp.async.ca.shared.global [%0], [%1], 16;\n" :: "r"(dst), "l"(src));
}
__device__ __forceinline__ void cpcommit() { asm volatile("cp.async.commit_group;\n"); }
__device__ __forceinline__ void cpwait1()  { asm volatile("cp.async.wait_group 1;\n"); }
__device__ __forceinline__ void cpwait0()  { asm volatile("cp.async.wait_group 0;\n"); }

// ---------- kernel 1: fused weight prep + input transpose + LN1 ------------
// blocks [0, 1728): weight transpose fp32[R][C] -> fp16[C][R]
// blocks [1728, 1984): x transpose + LN1 -> hnb
__global__ void __launch_bounds__(256)
k_prep(const float* __restrict__ x, const float* __restrict__ g1,
       const float* __restrict__ b1, __half* __restrict__ hn,
       const float* __restrict__ Wqkv, const float* __restrict__ Wo,
       const float* __restrict__ W1, const float* __restrict__ W2,
       __half* __restrict__ wqkv, __half* __restrict__ wo,
       __half* __restrict__ w1, __half* __restrict__ w2)
{
    __shared__ float smbuf[TT * (DIM + 1)];   // 24.6 KB; wprep uses a prefix
    const int tid = threadIdx.x;

    if (blockIdx.x < WPREP_BLOCKS) {
        // ---- weight prep: 32x32 tile transpose ----
        const int tx = tid & 31, ty = tid >> 5;
        int bid = blockIdx.x;
        const float* in; __half* out; int R, C, rb, cb;
        if (bid < 432)       { int id = bid;        in = Wqkv; out = wqkv; R = 384;  C = 1152; cb = id % 36; rb = id / 36; }
        else if (bid < 576)  { int id = bid - 432;  in = Wo;   out = wo;   R = 384;  C = 384;  cb = id % 12; rb = id / 12; }
        else if (bid < 1152) { int id = bid - 576;  in = W1;   out = w1;   R = 384;  C = 1536; cb = id % 48; rb = id / 48; }
        else                 { int id = bid - 1152; in = W2;   out = w2;   R = 1536; C = 384;  cb = id % 12; rb = id / 12; }

        float (*t)[33] = (float(*)[33])smbuf;
        const int c = cb * 32 + tx;
        #pragma unroll
        for (int j = 0; j < 4; j++) {
            int r = rb * 32 + ty + j * 8;
            t[ty + j * 8][tx] = in[(size_t)r * C + c];
        }
        __syncthreads();
        const int r2 = rb * 32 + tx;
        #pragma unroll
        for (int j = 0; j < 4; j++) {
            int c2 = cb * 32 + ty + j * 8;
            out[(size_t)c2 * R + r2] = __float2half(t[tx][ty + j * 8]);
        }
    } else {
        // ---- x transpose + LN1 ----
        float (*tile)[DIM + 1] = (float(*)[DIM + 1])smbuf;
        const int blk = blockIdx.x - WPREP_BLOCKS;
        const int tilesPerBatch = NTOK / TT;
        const int bb = blk / tilesPerBatch;
        const int n0 = (blk % tilesPerBatch) * TT;
        const float* xb = x + (size_t)bb * DIM * NTOK;

        for (int idx = tid; idx < DIM * TT; idx += 256) {
            int c = idx / TT, t = idx % TT;
            tile[t][c] = xb[(size_t)c * NTOK + n0 + t];
        }
        __syncthreads();

        const int wid = tid >> 5, lane = tid & 31;
        for (int t = wid; t < TT; t += 8) {
            float s = 0.f;
            #pragma unroll
            for (int c = lane; c < DIM; c += 32) s += tile[t][c];
            #pragma unroll
            for (int o = 16; o; o >>= 1) s += __shfl_xor_sync(0xffffffffu, s, o);
            float mu = s * (1.f / DIM);
            float vs = 0.f;
            #pragma unroll
            for (int c = lane; c < DIM; c += 32) { float d = tile[t][c] - mu; vs += d * d; }
            #pragma unroll
            for (int o = 16; o; o >>= 1) vs += __shfl_xor_sync(0xffffffffu, vs, o);
            float rstd = rsqrtf(vs * (1.f / DIM) + 1e-6f);
            size_t row = ((size_t)bb * NTOK + n0 + t) * DIM;
            for (int c = lane; c < DIM; c += 32) {
                hn[row + c] = __float2half((tile[t][c] - mu) * rstd * g1[c] + b1[c]);
            }
        }
    }
}

// ----------------- kernel 2: fp16 GEMM (ldmatrix + cp.async) ---------------
// RESTR: residual read from x in [B][DIM][NTOK]. OUTTR: transposed fp32 out.
template<int BM, bool BIAS, bool GELU_, bool RES, bool RESTR, bool OUTHF, bool OUTTR>
__global__ void __launch_bounds__(256)
k_gemm(const __half* __restrict__ A, const __half* __restrict__ Bt,
       const float* __restrict__ bias, const float* __restrict__ res,
       void* __restrict__ Cout, int M, int N, int K)
{
    constexpr int BN = 64, BK = 32;
    constexpr int SA = 40;
    constexpr int MW = BM / 32;
    constexpr int WN = BN / (8 / MW);
    constexpr int NS = WN / 8;
    __shared__ __half As[2][BM * SA];
    __shared__ __half Bs[2][BN * SA];

    const int tid = threadIdx.x;
    const int m0 = blockIdx.y * BM, n0 = blockIdx.x * BN;
    const int wid = tid >> 5, lane = tid & 31;
    const int g = lane >> 2, tg = lane & 3;
    const int wm0 = (wid % MW) * 32;
    const int wn0 = (wid / MW) * WN;
    const int lr = lane & 15, lk = (lane >> 4) * 8;

    float acc[2][NS][4];
    #pragma unroll
    for (int i = 0; i < 2; i++)
        #pragma unroll
        for (int j = 0; j < NS; j++)
            #pragma unroll
            for (int q = 0; q < 4; q++) acc[i][j][q] = 0.f;

    const int a_r = tid >> 2, a_c = (tid & 3) * 8;
    const __half* Ap = A  + (size_t)(m0 + a_r) * K + a_c;
    const __half* Bp = Bt + (size_t)(n0 + a_r) * K + a_c;

    uint32_t sA[2], sA2[2], sB[2];
    #pragma unroll
    for (int bset = 0; bset < 2; bset++) {
        sA[bset]  = smaddr(&As[bset][a_r * SA + a_c]);
        sA2[bset] = smaddr(&As[bset][(a_r + 64) * SA + a_c]);
        sB[bset]  = smaddr(&Bs[bset][a_r * SA + a_c]);
    }

    const int ntiles = K / BK;
    cpasync16(sA[0], Ap);
    if (BM == 128) cpasync16(sA2[0], Ap + (size_t)64 * K);
    cpasync16(sB[0], Bp);
    cpcommit();

    for (int t = 0; t < ntiles; t++) {
        const int cur = t & 1;
        if (t + 1 < ntiles) {
            const __half* an = Ap + (t + 1) * BK;
            const __half* bn = Bp + (t + 1) * BK;
            cpasync16(sA[cur ^ 1], an);
            if (BM == 128) cpasync16(sA2[cur ^ 1], an + (size_t)64 * K);
            cpasync16(sB[cur ^ 1], bn);
            cpcommit();
            cpwait1();
        } else {
            cpwait0();
        }
        __syncthreads();

        #pragma unroll
        for (int kk = 0; kk < 2; kk++) {
            uint32_t af[2][4];
            #pragma unroll
            for (int ms = 0; ms < 2; ms++)
                ldsm4(af[ms], smaddr(&As[cur][(wm0 + ms * 16 + lr) * SA + kk * 16 + lk]));
            #pragma unroll
            for (int p = 0; p < NS / 2; p++) {
                uint32_t bf[4];
                ldsm4(bf, smaddr(&Bs[cur][(wn0 + p * 16 + lr) * SA + kk * 16 + lk]));
                #pragma unroll
                for (int ms = 0; ms < 2; ms++) {
                    mma16(acc[ms][2 * p],     af[ms], bf[0], bf[2]);
                    mma16(acc[ms][2 * p + 1], af[ms], bf[1], bf[3]);
                }
            }
        }
        __syncthreads();
    }

    #pragma unroll
    for (int ms = 0; ms < 2; ms++) {
        #pragma unroll
        for (int rr = 0; rr < 2; rr++) {
            size_t m = (size_t)m0 + wm0 + ms * 16 + g + rr * 8;
            #pragma unroll
            for (int ns = 0; ns < NS; ns++) {
                int n = n0 + wn0 + ns * 8 + tg * 2;
                float v0 = acc[ms][ns][rr * 2 + 0];
                float v1 = acc[ms][ns][rr * 2 + 1];
                if (BIAS) { v0 += bias[n]; v1 += bias[n + 1]; }
                if (GELU_) {
                    v0 = 0.5f * v0 * (1.f + erff(v0 * 0.70710678118654752f));
                    v1 = 0.5f * v1 * (1.f + erff(v1 * 0.70710678118654752f));
                }
                if (RES) {
                    if (RESTR) {
                        int bbb = (int)(m >> 11), tok = (int)(m & (NTOK - 1));
                        v0 += res[((size_t)bbb * DIM + n) * NTOK + tok];
                        v1 += res[((size_t)bbb * DIM + n + 1) * NTOK + tok];
                    } else {
                        v0 += res[m * N + n];
                        v1 += res[m * N + n + 1];
                    }
                }
                if (OUTTR) {
                    int bbb = (int)(m >> 11), tok = (int)(m & (NTOK - 1));
                    float* op = (float*)Cout + ((size_t)bbb * DIM + n) * NTOK + tok;
                    op[0] = v0;
                    op[NTOK] = v1;
                } else if (OUTHF) {
                    *(__half2*)((__half*)Cout + m * N + n) = __floats2half2_rn(v0, v1);
                } else {
                    *(float2*)((float*)Cout + m * N + n) = make_float2(v0, v1);
                }
            }
        }
    }
}

// ---------------- kernel 3: split-KV fp16 flash attention ------------------
// grid (NTOK/64, BH, SPLIT). BQ=64 (4 warps x 16 rows). Q staged via Ks[0].
__global__ void __launch_bounds__(128)
k_attn(const __half* __restrict__ qkv,
       __half* __restrict__ po, float* __restrict__ pm, float* __restrict__ pl)
{
    constexpr int SQ = 56;
    __shared__ __half Ks[2][64 * SQ];
    __shared__ __half Vs[2][64 * SQ];

    const int bh = blockIdx.y;
    const int sp = blockIdx.z;
    const int bb = bh >> 3, hh = bh & 7;
    const __half* base = qkv + (size_t)bb * NTOK * QKVC + hh * HDIM;
    const __half* kvbase = base + (size_t)sp * TILES_PER_SPLIT * 64 * QKVC;
    const int q0 = blockIdx.x * 64;
    const int tid = threadIdx.x;
    const int w = tid >> 5, lane = tid & 31;
    const int g = lane >> 2, tg = lane & 3;
    const int wrow0 = w * 16;
    const int lr = lane & 15, lk = (lane >> 4) * 8;

    #pragma unroll
    for (int j = 0; j < 3; j++) {
        int idx = tid + j * 128;
        int r = idx / 6, c8 = (idx % 6) * 8;
        *(uint4*)&Ks[0][r * SQ + c8] = *(const uint4*)(base + (size_t)(q0 + r) * QKVC + c8);
    }
    __syncthreads();
    uint32_t aq[3][4];
    #pragma unroll
    for (int kc = 0; kc < 3; kc++)
        ldsm4(aq[kc], smaddr(&Ks[0][(wrow0 + lr) * SQ + kc * 16 + lk]));
    __syncthreads();

    const int r0i = (tid) / 6, c0i = ((tid) % 6) * 8;
    const int r1i = (tid + 128) / 6, c1i = ((tid + 128) % 6) * 8;
    const int r2i = (tid + 256) / 6, c2i = ((tid + 256) % 6) * 8;
    const size_t o0 = (size_t)r0i * QKVC + c0i;
    const size_t o1 = (size_t)r1i * QKVC + c1i;
    const size_t o2 = (size_t)r2i * QKVC + c2i;

    cpasync16(smaddr(&Ks[0][r0i * SQ + c0i]), kvbase + o0 + DIM);
    cpasync16(smaddr(&Ks[0][r1i * SQ + c1i]), kvbase + o1 + DIM);
    cpasync16(smaddr(&Ks[0][r2i * SQ + c2i]), kvbase + o2 + DIM);
    cpasync16(smaddr(&Vs[0][r0i * SQ + c0i]), kvbase + o0 + 2 * DIM);
    cpasync16(smaddr(&Vs[0][r1i * SQ + c1i]), kvbase + o1 + 2 * DIM);
    cpasync16(smaddr(&Vs[0][r2i * SQ + c2i]), kvbase + o2 + 2 * DIM);
    cpcommit();

    float oacc[6][4], lacc[4];
    #pragma unroll
    for (int i = 0; i < 6; i++)
        #pragma unroll
        for (int j = 0; j < 4; j++) oacc[i][j] = 0.f;
    #pragma unroll
    for (int j = 0; j < 4; j++) lacc[j] = 0.f;
    float mA = -1e30f, mB = -1e30f;

    for (int kt = 0; kt < TILES_PER_SPLIT; kt++) {
        const int cur = kt & 1;
        if (kt + 1 < TILES_PER_SPLIT) {
            const __half* nb = kvbase + (size_t)(kt + 1) * 64 * QKVC;
            cpasync16(smaddr(&Ks[cur ^ 1][r0i * SQ + c0i]), nb + o0 + DIM);
            cpasync16(smaddr(&Ks[cur ^ 1][r1i * SQ + c1i]), nb + o1 + DIM);
            cpasync16(smaddr(&Ks[cur ^ 1][r2i * SQ + c2i]), nb + o2 + DIM);
            cpasync16(smaddr(&Vs[cur ^ 1][r0i * SQ + c0i]), nb + o0 + 2 * DIM);
            cpasync16(smaddr(&Vs[cur ^ 1][r1i * SQ + c1i]), nb + o1 + 2 * DIM);
            cpasync16(smaddr(&Vs[cur ^ 1][r2i * SQ + c2i]), nb + o2 + 2 * DIM);
            cpcommit();
            cpwait1();
        } else {
            cpwait0();
        }
        __syncthreads();

        float sacc[8][4];
        #pragma unroll
        for (int ns = 0; ns < 8; ns++)
            #pragma unroll
            for (int q = 0; q < 4; q++) sacc[ns][q] = 0.f;
        #pragma unroll
        for (int kc = 0; kc < 3; kc++) {
            #pragma unroll
            for (int p = 0; p < 4; p++) {
                uint32_t bk[4];
                ldsm4(bk, smaddr(&Ks[cur][(p * 16 + lr) * SQ + kc * 16 + lk]));
                mma16(sacc[2 * p],     aq[kc], bk[0], bk[2]);
                mma16(sacc[2 * p + 1], aq[kc], bk[1], bk[3]);
            }
        }

        float rmaxA = -1e30f, rmaxB = -1e30f;
        #pragma unroll
        for (int ns = 0; ns < 8; ns++) {
            rmaxA = fmaxf(rmaxA, fmaxf(sacc[ns][0], sacc[ns][1]));
            rmaxB = fmaxf(rmaxB, fmaxf(sacc[ns][2], sacc[ns][3]));
        }
        rmaxA = fmaxf(rmaxA, __shfl_xor_sync(0xffffffffu, rmaxA, 1));
        rmaxA = fmaxf(rmaxA, __shfl_xor_sync(0xffffffffu, rmaxA, 2));
        rmaxB = fmaxf(rmaxB, __shfl_xor_sync(0xffffffffu, rmaxB, 1));
        rmaxB = fmaxf(rmaxB, __shfl_xor_sync(0xffffffffu, rmaxB, 2));

        float mAn = fmaxf(mA, rmaxA), mBn = fmaxf(mB, rmaxB);
        float fA = exp2f((mA - mAn) * ATT_C), fB = exp2f((mB - mBn) * ATT_C);
        mA = mAn; mB = mBn;
        const float nmcA = -mA * ATT_C, nmcB = -mB * ATT_C;

        uint32_t pA[8], pB[8];
        #pragma unroll
        for (int ns = 0; ns < 8; ns++) {
            pA[ns] = ex2h2(fmaf(sacc[ns][0], ATT_C, nmcA),
                           fmaf(sacc[ns][1], ATT_C, nmcA));
            pB[ns] = ex2h2(fmaf(sacc[ns][2], ATT_C, nmcB),
                           fmaf(sacc[ns][3], ATT_C, nmcB));
        }

        #pragma unroll
        for (int ns = 0; ns < 6; ns++) {
            oacc[ns][0] *= fA; oacc[ns][1] *= fA;
            oacc[ns][2] *= fB; oacc[ns][3] *= fB;
        }
        lacc[0] *= fA; lacc[1] *= fA; lacc[2] *= fB; lacc[3] *= fB;

        #pragma unroll
        for (int kc = 0; kc < 4; kc++) {
            uint32_t ap[4] = { pA[2 * kc], pB[2 * kc], pA[2 * kc + 1], pB[2 * kc + 1] };
            #pragma unroll
            for (int p = 0; p < 3; p++) {
                uint32_t bv[4];
                ldsm4t(bv, smaddr(&Vs[cur][(kc * 16 + lr) * SQ + p * 16 + lk]));
                mma16(oacc[2 * p],     ap, bv[0], bv[1]);
                mma16(oacc[2 * p + 1], ap, bv[2], bv[3]);
            }
            mma16(lacc, ap, ONES_H2, ONES_H2);
        }
        __syncthreads();
    }

    const size_t prowA = ((size_t)(sp * BH + bh) * NTOK) + q0 + wrow0 + g;
    #pragma unroll
    for (int ns = 0; ns < 6; ns++) {
        int col = ns * 8 + tg * 2;
        *(__half2*)&po[prowA * HDIM + col] = __floats2half2_rn(oacc[ns][0], oacc[ns][1]);
        *(__half2*)&po[(prowA + 8) * HDIM + col] = __floats2half2_rn(oacc[ns][2], oacc[ns][3]);
    }
    if (tg == 0) {
        pm[prowA] = mA; pl[prowA] = lacc[0];
        pm[prowA + 8] = mB; pl[prowA + 8] = lacc[2];
    }
}

// ---------------- kernel 3b: split-KV merge (half2 vectorized) -------------
__global__ void k_attn_merge(const __half* __restrict__ po, const float* __restrict__ pm,
                             const float* __restrict__ pl, __half* __restrict__ attn)
{
    const int e = blockIdx.x * 256 + threadIdx.x;     // element pair index
    if (e >= BH * NTOK * (HDIM / 2)) return;
    const int d2 = e % (HDIM / 2);
    const int row = e / (HDIM / 2);                   // bh*NTOK + q
    float m = -1e30f;
    #pragma unroll
    for (int s = 0; s < SPLIT; s++) m = fmaxf(m, pm[s * BH * NTOK + row]);
    float n0 = 0.f, n1 = 0.f, den = 0.f;
    #pragma unroll
    for (int s = 0; s < SPLIT; s++) {
        const float ws = exp2f((pm[s * BH * NTOK + row] - m) * ATT_C);
        const __half2 o2 = *(const __half2*)&po[((size_t)s * BH * NTOK + row) * HDIM + d2 * 2];
        const float2 of = __half22float2(o2);
        n0 += of.x * ws;
        n1 += of.y * ws;
        den += pl[s * BH * NTOK + row] * ws;
    }
    const float inv = 1.f / den;
    const int bh = row >> 11, q = row & (NTOK - 1);
    const int bb = bh >> 3, hh = bh & 7;
    *(__half2*)&attn[((size_t)(bb * NTOK + q)) * DIM + hh * HDIM + d2 * 2] =
        __floats2half2_rn(n0 * inv, n1 * inv);
}

// --------------------------- kernel 4: LN ---------------------------------
__global__ void k_ln(const float* __restrict__ in, const float* __restrict__ g,
                     const float* __restrict__ b, __half* __restrict__ out)
{
    const int row = blockIdx.x;
    const float* p = in + (size_t)row * DIM;
    const int t = threadIdx.x;
    float v0 = p[t], v1 = p[t + 128], v2 = p[t + 256];
    float s = v0 + v1 + v2;

    __shared__ float red[4];
    #pragma unroll
    for (int o = 16; o; o >>= 1) s += __shfl_xor_sync(0xffffffffu, s, o);
    if ((t & 31) == 0) red[t >> 5] = s;
    __syncthreads();
    float mu = (red[0] + red[1] + red[2] + red[3]) * (1.f / DIM);

    float d0 = v0 - mu, d1 = v1 - mu, d2 = v2 - mu;
    float q = d0 * d0 + d1 * d1 + d2 * d2;
    __syncthreads();
    #pragma unroll
    for (int o = 16; o; o >>= 1) q += __shfl_xor_sync(0xffffffffu, q, o);
    if ((t & 31) == 0) red[t >> 5] = q;
    __syncthreads();
    float rstd = rsqrtf((red[0] + red[1] + red[2] + red[3]) * (1.f / DIM) + 1e-6f);

    __half* po = out + (size_t)row * DIM;
    po[t]       = __float2half(d0 * rstd * g[t]       + b[t]);
    po[t + 128] = __float2half(d1 * rstd * g[t + 128] + b[t + 128]);
    po[t + 256] = __float2half(d2 * rstd * g[t + 256] + b[t + 256]);
}

// ------------------------------- launch ------------------------------------
extern "C" void kernel_launch(void* const* d_in, const int* in_sizes, int n_in,
                              void* d_out, int out_size)
{
    const float* x    = (const float*)d_in[0];
    const float* g1   = (const float*)d_in[1];
    const float* b1   = (const float*)d_in[2];
    const float* Wqkv = (const float*)d_in[3];
    const float* Wo   = (const float*)d_in[4];
    const float* bo   = (const float*)d_in[5];
    const float* g2   = (const float*)d_in[6];
    const float* b2   = (const float*)d_in[7];
    const float* W1   = (const float*)d_in[8];
    const float* b1m  = (const float*)d_in[9];
    const float* W2   = (const float*)d_in[10];
    const float* b2m  = (const float*)d_in[11];
    float* out = (float*)d_out;

    float *h, *pm, *pl;
    __half *hnb, *qkvb, *attb, *mlpb, *wqkv, *wo, *w1, *w2, *po;
    cudaGetSymbolAddress((void**)&h,    g_h);
    cudaGetSymbolAddress((void**)&hnb,  g_hnb);
    cudaGetSymbolAddress((void**)&qkvb, g_qkvb);
    cudaGetSymbolAddress((void**)&attb, g_attb);
    cudaGetSymbolAddress((void**)&mlpb, g_mlpb);
    cudaGetSymbolAddress((void**)&wqkv, g_wqkv);
    cudaGetSymbolAddress((void**)&wo,   g_wo);
    cudaGetSymbolAddress((void**)&w1,   g_w1);
    cudaGetSymbolAddress((void**)&w2,   g_w2);
    cudaGetSymbolAddress((void**)&po,   g_po);
    cudaGetSymbolAddress((void**)&pm,   g_pm);
    cudaGetSymbolAddress((void**)&pl,   g_pl);

    // 1. fused: weight prep + transpose + LN1
    k_prep<<<WPREP_BLOCKS + MTOT / TT, 256>>>(x, g1, b1, hnb,
                                              Wqkv, Wo, W1, W2,
                                              wqkv, wo, w1, w2);
    // 2. qkv = hn @ Wqkv
    k_gemm<128, false, false, false, false, true, false>
        <<<dim3(QKVC / 64, MTOT / 128), 256>>>(
        hnb, wqkv, nullptr, nullptr, qkvb, MTOT, QKVC, DIM);
    // 3. attention (split-KV x2) + merge
    k_attn<<<dim3(NTOK / 64, BH, SPLIT), 128>>>(qkvb, po, pm, pl);
    k_attn_merge<<<(BH * NTOK * (HDIM / 2) + 255) / 256, 256>>>(po, pm, pl, attb);
    // 4. h = x(transposed) + att @ Wo + bo
    k_gemm<64, true, false, true, true, false, false>
        <<<dim3(DIM / 64, MTOT / 64), 256>>>(
        attb, wo, bo, x, h, MTOT, DIM, DIM);
    // 5. LN2
    k_ln<<<MTOT, 128>>>(h, g2, b2, hnb);
    // 6. mlp = gelu(hn @ W1 + b1m)
    k_gemm<128, true, true, false, false, true, false>
        <<<dim3(MLPH / 64, MTOT / 128), 256>>>(
        hnb, w1, b1m, nullptr, mlpb, MTOT, MLPH, DIM);
    // 7. out = transpose(h + mlp @ W2 + b2m)
    k_gemm<64, true, false, true, false, false, true>
        <<<dim3(DIM / 64, MTOT / 64), 256>>>(
        mlpb, w2, b2m, h, out, MTOT, DIM, MLPH);
}